// round 3
// baseline (speedup 1.0000x reference)
#include <cuda_runtime.h>
#include <math.h>

// Problem constants
#define B_   32
#define C_   512
#define HW_  3136          // 56*56
#define N_   27
#define NPIX (B_*HW_)      // 100352 pixels
#define CCHUNK  128        // channels per smem tile
#define NCHUNKS (C_/CCHUNK)
#define ROWPAD  56         // floats per channel row: 27 duplicated pairs = 54, pad to 56 (224B)
#define PF     8           // prefetch depth (channels per batch)
#define NBATCH (CCHUNK/PF) // 16 batches per chunk
#define F4STRIDE (HW_/4)   // float4 stride between channels = 784
#define TPB    64          // threads per block
#define PXT    4           // pixels per thread

// Scratch (no device allocation allowed)
__device__ float    g_cl[N_ * C_];   // normalized clusters, [n][c]
__device__ double   g_loss;
__device__ unsigned g_done;

// ---------------------------------------------------------------------------
// packed f32x2 helpers (sm_103a)
// ---------------------------------------------------------------------------
__device__ __forceinline__ unsigned long long packf2(float x, float y) {
    unsigned long long r;
    asm("mov.b64 %0, {%1, %2};" : "=l"(r) : "f"(x), "f"(y));
    return r;
}
__device__ __forceinline__ void unpackf2(unsigned long long d, float& x, float& y) {
    asm("mov.b64 {%0, %1}, %2;" : "=f"(x), "=f"(y) : "l"(d));
}
#define FMA2(d, a, b) asm("fma.rn.f32x2 %0, %1, %2, %0;" : "+l"(d) : "l"(a), "l"(b))

// ---------------------------------------------------------------------------
// Kernel 0: normalize cluster rows (27 blocks x 512 threads)
// ---------------------------------------------------------------------------
__global__ void prep_kernel(const float* __restrict__ clusters) {
    int n   = blockIdx.x;
    int tid = threadIdx.x;

    float v = clusters[n * C_ + tid];
    float p = v * v;
    #pragma unroll
    for (int o = 16; o; o >>= 1) p += __shfl_xor_sync(0xffffffffu, p, o);

    __shared__ float ws[16];
    if ((tid & 31) == 0) ws[tid >> 5] = p;
    __syncthreads();
    float tot = 0.f;
    #pragma unroll
    for (int w = 0; w < 16; ++w) tot += ws[w];
    float inv = 1.f / fmaxf(sqrtf(tot), 1e-12f);

    g_cl[n * C_ + tid] = v * inv;

    if (n == 0 && tid == 0) { g_loss = 0.0; }
}

// ---------------------------------------------------------------------------
// Kernel 1: main fused kernel. 4 pixels per thread (two f32x2 pairs) so each
// cluster LDS.128 feeds 8 FMA2 lanes -> LDS pipe halved vs 2-px version.
// 392 blocks x 64 threads, ~200 regs, 4 blocks/SM, one full wave.
// ---------------------------------------------------------------------------
__global__ void __launch_bounds__(TPB, 4)
main_kernel(const float* __restrict__ x, float* __restrict__ out,
            int probs_off, int write_loss, int nblocks) {
    __shared__ __align__(16) float sCl[CCHUNK * ROWPAD];

    int qIdx = blockIdx.x * TPB + threadIdx.x;
    int p0 = qIdx * PXT;                  // HW_ % 4 == 0 -> quad never crosses b
    int b  = p0 / HW_;
    int hw = p0 - b * HW_;

    const float4* xp = reinterpret_cast<const float4*>(x)
                     + ((size_t)b * C_ * HW_ + hw) / 4;

    unsigned long long accA[N_], accB[N_];
    unsigned long long ssqA = 0ull, ssqB = 0ull;
    #pragma unroll
    for (int n = 0; n < N_; ++n) { accA[n] = 0ull; accB[n] = 0ull; }

    float4 bufA[PF], bufB[PF];

    for (int ch = 0; ch < NCHUNKS; ++ch) {
        const float4* xc = xp + (size_t)ch * CCHUNK * F4STRIDE;

        // prefetch batch 0 of this chunk BEFORE the fill barrier (hides the bubble)
        #pragma unroll
        for (int k = 0; k < PF; ++k) bufA[k] = xc[k * F4STRIDE];

        __syncthreads();   // protect prior-chunk smem reads
        {   // fill smem tile: 64 threads, 128 channels -> 2 channels per thread
            #pragma unroll
            for (int r = 0; r < CCHUNK / TPB; ++r) {
                int cc = threadIdx.x + r * TPB;
                int cbase = ch * CCHUNK + cc;
                #pragma unroll
                for (int n = 0; n < N_; ++n) {
                    float v = g_cl[n * C_ + cbase];
                    sCl[cc * ROWPAD + 2 * n]     = v;
                    sCl[cc * ROWPAD + 2 * n + 1] = v;
                }
            }
        }
        __syncthreads();

        #pragma unroll 1
        for (int bt = 0; bt < NBATCH; bt += 2) {
            // prefetch batch bt+1
            {
                const float4* xb = xc + (size_t)(bt + 1) * PF * F4STRIDE;
                #pragma unroll
                for (int k = 0; k < PF; ++k) bufB[k] = xb[k * F4STRIDE];
            }
            // compute batch bt from bufA
            #pragma unroll
            for (int k = 0; k < PF; ++k) {
                unsigned long long xa = packf2(bufA[k].x, bufA[k].y);
                unsigned long long xb2 = packf2(bufA[k].z, bufA[k].w);
                FMA2(ssqA, xa, xa);
                FMA2(ssqB, xb2, xb2);
                const float* row = &sCl[(bt * PF + k) * ROWPAD];
                const double2* crow = reinterpret_cast<const double2*>(row);
                #pragma unroll
                for (int j = 0; j < 13; ++j) {
                    double2 d = crow[j];
                    unsigned long long c0 = __double_as_longlong(d.x);
                    unsigned long long c1 = __double_as_longlong(d.y);
                    FMA2(accA[2 * j],     xa,  c0);
                    FMA2(accB[2 * j],     xb2, c0);
                    FMA2(accA[2 * j + 1], xa,  c1);
                    FMA2(accB[2 * j + 1], xb2, c1);
                }
                unsigned long long ct = __double_as_longlong(
                    *reinterpret_cast<const double*>(row + 52));
                FMA2(accA[26], xa,  ct);
                FMA2(accB[26], xb2, ct);
            }
            // prefetch batch bt+2 (or batch 0 of next chunk is handled at loop top)
            if (bt + 2 < NBATCH) {
                const float4* xb = xc + (size_t)(bt + 2) * PF * F4STRIDE;
                #pragma unroll
                for (int k = 0; k < PF; ++k) bufA[k] = xb[k * F4STRIDE];
            }
            // compute batch bt+1 from bufB
            #pragma unroll
            for (int k = 0; k < PF; ++k) {
                unsigned long long xa = packf2(bufB[k].x, bufB[k].y);
                unsigned long long xb2 = packf2(bufB[k].z, bufB[k].w);
                FMA2(ssqA, xa, xa);
                FMA2(ssqB, xb2, xb2);
                const float* row = &sCl[((bt + 1) * PF + k) * ROWPAD];
                const double2* crow = reinterpret_cast<const double2*>(row);
                #pragma unroll
                for (int j = 0; j < 13; ++j) {
                    double2 d = crow[j];
                    unsigned long long c0 = __double_as_longlong(d.x);
                    unsigned long long c1 = __double_as_longlong(d.y);
                    FMA2(accA[2 * j],     xa,  c0);
                    FMA2(accB[2 * j],     xb2, c0);
                    FMA2(accA[2 * j + 1], xa,  c1);
                    FMA2(accB[2 * j + 1], xb2, c1);
                }
                unsigned long long ct = __double_as_longlong(
                    *reinterpret_cast<const double*>(row + 52));
                FMA2(accA[26], xa,  ct);
                FMA2(accB[26], xb2, ct);
            }
        }
    }

    // ---------------- epilogue: normalize, softmax, store, loss ----------------
    float q0, q1, q2, q3;
    unpackf2(ssqA, q0, q1);
    unpackf2(ssqB, q2, q3);
    float inv0 = 1.f / fmaxf(sqrtf(q0), 1e-12f);
    float inv1 = 1.f / fmaxf(sqrtf(q1), 1e-12f);
    float inv2 = 1.f / fmaxf(sqrtf(q2), 1e-12f);
    float inv3 = 1.f / fmaxf(sqrtf(q3), 1e-12f);

    float s0[N_], s1[N_], s2[N_], s3[N_];
    float m0 = -1e30f, m1 = -1e30f, m2 = -1e30f, m3 = -1e30f;
    #pragma unroll
    for (int n = 0; n < N_; ++n) {
        float a0, a1, a2, a3;
        unpackf2(accA[n], a0, a1);
        unpackf2(accB[n], a2, a3);
        s0[n] = a0 * inv0;  s1[n] = a1 * inv1;
        s2[n] = a2 * inv2;  s3[n] = a3 * inv3;
        m0 = fmaxf(m0, s0[n]);  m1 = fmaxf(m1, s1[n]);
        m2 = fmaxf(m2, s2[n]);  m3 = fmaxf(m3, s3[n]);
    }
    float t0 = 0.f, t1 = 0.f, t2 = 0.f, t3 = 0.f;
    #pragma unroll
    for (int n = 0; n < N_; ++n) {
        t0 += __expf(2.f * (s0[n] - m0));
        t1 += __expf(2.f * (s1[n] - m1));
        t2 += __expf(2.f * (s2[n] - m2));
        t3 += __expf(2.f * (s3[n] - m3));
    }
    float r0 = 1.f / t0, r1 = 1.f / t1, r2 = 1.f / t2, r3 = 1.f / t3;

    float* po = out + probs_off + (size_t)b * N_ * HW_ + hw;
    float lp = 0.f;
    #pragma unroll
    for (int n = 0; n < N_; ++n) {
        float pv0 = __expf(2.f * (s0[n] - m0)) * r0;
        float pv1 = __expf(2.f * (s1[n] - m1)) * r1;
        float pv2 = __expf(2.f * (s2[n] - m2)) * r2;
        float pv3 = __expf(2.f * (s3[n] - m3)) * r3;
        float* pn = po + (size_t)n * HW_;
        pn[0] = pv0; pn[1] = pv1; pn[2] = pv2; pn[3] = pv3;
        lp += pv0 * s0[n] + pv1 * s1[n] + pv2 * s2[n] + pv3 * s3[n];
    }

    // loss partial: warp reduce + one atomic per warp
    #pragma unroll
    for (int o = 16; o; o >>= 1) lp += __shfl_xor_sync(0xffffffffu, lp, o);
    if ((threadIdx.x & 31) == 0) atomicAdd(&g_loss, (double)lp);

    // last-block finalization
    __shared__ unsigned s_last;
    __syncthreads();
    if (threadIdx.x == 0) {
        __threadfence();
        s_last = (atomicAdd(&g_done, 1u) == (unsigned)(nblocks - 1));
    }
    __syncthreads();
    if (s_last && threadIdx.x == 0) {
        double L = *(volatile double*)&g_loss;
        if (write_loss) out[0] = (float)(-L / (double)NPIX);
        g_done = 0u;
    }
}

// ---------------------------------------------------------------------------
extern "C" void kernel_launch(void* const* d_in, const int* in_sizes, int n_in,
                              void* d_out, int out_size) {
    const float* x        = (const float*)d_in[0];
    const float* clusters = (const float*)d_in[1];
    if (in_sizes[0] == N_ * C_) {
        x        = (const float*)d_in[1];
        clusters = (const float*)d_in[0];
    }
    float* out = (float*)d_out;

    int probs_off  = out_size - (B_ * N_ * HW_);
    if (probs_off < 0) probs_off = 0;
    int write_loss = (probs_off >= 1) ? 1 : 0;

    int nblocks = NPIX / PXT / TPB;          // 392
    prep_kernel<<<N_, 512>>>(clusters);
    main_kernel<<<nblocks, TPB>>>(x, out, probs_off, write_loss, nblocks);
}

// round 4
// speedup vs baseline: 1.7442x; 1.7442x over previous
#include <cuda_runtime.h>
#include <math.h>

// Problem constants
#define B_   32
#define C_   512
#define HW_  3136          // 56*56
#define N_   27
#define NPIX (B_*HW_)      // 100352 pixels
#define CCHUNK  128        // channels per smem tile
#define NCHUNKS (C_/CCHUNK)
#define ROWF   28          // floats per channel row in smem: 27 clusters + 1 zero pad (112B)
#define NPAIR  14          // f32x2 accumulator pairs per pixel
#define PF     8           // prefetch depth (channels per batch)
#define NBATCH (CCHUNK/PF)
#define F2STRIDE (HW_/2)   // float2 stride between channels = 1568

// Scratch (no device allocation allowed)
__device__ float    g_cl[N_ * C_];   // normalized clusters, [n][c]
__device__ double   g_loss;
__device__ unsigned g_done;

// ---------------------------------------------------------------------------
// packed f32x2 helpers (sm_103a)
// ---------------------------------------------------------------------------
__device__ __forceinline__ unsigned long long packf2(float x, float y) {
    unsigned long long r;
    asm("mov.b64 %0, {%1, %2};" : "=l"(r) : "f"(x), "f"(y));
    return r;
}
__device__ __forceinline__ void unpackf2(unsigned long long d, float& x, float& y) {
    asm("mov.b64 {%0, %1}, %2;" : "=f"(x), "=f"(y) : "l"(d));
}
#define FMA2(d, a, b) asm("fma.rn.f32x2 %0, %1, %2, %0;" : "+l"(d) : "l"(a), "l"(b))

// ---------------------------------------------------------------------------
// Kernel 0: normalize cluster rows (27 blocks x 512 threads)
// ---------------------------------------------------------------------------
__global__ void prep_kernel(const float* __restrict__ clusters) {
    int n   = blockIdx.x;
    int tid = threadIdx.x;

    float v = clusters[n * C_ + tid];
    float p = v * v;
    #pragma unroll
    for (int o = 16; o; o >>= 1) p += __shfl_xor_sync(0xffffffffu, p, o);

    __shared__ float ws[16];
    if ((tid & 31) == 0) ws[tid >> 5] = p;
    __syncthreads();
    float tot = 0.f;
    #pragma unroll
    for (int w = 0; w < 16; ++w) tot += ws[w];
    float inv = 1.f / fmaxf(sqrtf(tot), 1e-12f);

    g_cl[n * C_ + tid] = v * inv;

    if (n == 0 && tid == 0) { g_loss = 0.0; }
}

// ---------------------------------------------------------------------------
// Kernel 1: main fused kernel. 2 pixels/thread. x is the broadcast operand
// ({x,x} built by a reg MOV); clusters come from smem NON-duplicated, so one
// LDS.128 yields 4 distinct cluster values = two f32x2 operands shared by
// both pixels. 7 LDS.128 per channel (vs 14 before). Accumulators are
// pairs-over-N: accP[pixel][j] = dots for clusters (2j, 2j+1).
// 392 blocks x 128 threads, 3 blocks/SM.
// ---------------------------------------------------------------------------
__global__ void __launch_bounds__(128, 3)
main_kernel(const float* __restrict__ x, float* __restrict__ out,
            int probs_off, int write_loss, int nblocks) {
    __shared__ __align__(16) float sCl[CCHUNK * ROWF];

    int pairIdx = blockIdx.x * 128 + threadIdx.x;
    int p0 = pairIdx * 2;                 // HW_ even -> pair never crosses b
    int b  = p0 / HW_;
    int hw = p0 - b * HW_;

    const float2* xp = reinterpret_cast<const float2*>(x)
                     + ((size_t)b * C_ * HW_ + hw) / 2;

    unsigned long long acc0[NPAIR], acc1[NPAIR];   // per-pixel pairs over N
    unsigned long long ssq = 0ull;                 // {ssq_px0, ssq_px1}
    #pragma unroll
    for (int j = 0; j < NPAIR; ++j) { acc0[j] = 0ull; acc1[j] = 0ull; }

    float2 bufA[PF], bufB[PF];

    for (int ch = 0; ch < NCHUNKS; ++ch) {
        const float2* xc = xp + (size_t)ch * CCHUNK * F2STRIDE;

        // prefetch batch 0 of this chunk before the fill barrier
        #pragma unroll
        for (int k = 0; k < PF; ++k) bufA[k] = xc[k * F2STRIDE];

        __syncthreads();   // protect prior-chunk smem reads
        {   // fill smem tile: thread tid owns channel tid (non-duplicated row)
            int cc = threadIdx.x;
            int cbase = ch * CCHUNK + cc;
            #pragma unroll
            for (int n = 0; n < N_; ++n)
                sCl[cc * ROWF + n] = g_cl[n * C_ + cbase];
            sCl[cc * ROWF + N_] = 0.f;    // pad slot 27
        }
        __syncthreads();

        #pragma unroll 1
        for (int bt = 0; bt < NBATCH; bt += 2) {
            {   // prefetch batch bt+1
                const float2* xb = xc + (size_t)(bt + 1) * PF * F2STRIDE;
                #pragma unroll
                for (int k = 0; k < PF; ++k) bufB[k] = xb[k * F2STRIDE];
            }
            // compute batch bt from bufA
            #pragma unroll
            for (int k = 0; k < PF; ++k) {
                float2 xv = bufA[k];
                unsigned long long x01 = packf2(xv.x, xv.y);
                FMA2(ssq, x01, x01);
                unsigned long long xb0 = packf2(xv.x, xv.x);
                unsigned long long xb1 = packf2(xv.y, xv.y);
                const double2* crow = reinterpret_cast<const double2*>(
                    &sCl[(bt * PF + k) * ROWF]);
                #pragma unroll
                for (int j = 0; j < 7; ++j) {
                    double2 d = crow[j];                 // clusters 4j..4j+3
                    unsigned long long cA = __double_as_longlong(d.x);
                    unsigned long long cB = __double_as_longlong(d.y);
                    FMA2(acc0[2 * j],     xb0, cA);
                    FMA2(acc1[2 * j],     xb1, cA);
                    FMA2(acc0[2 * j + 1], xb0, cB);
                    FMA2(acc1[2 * j + 1], xb1, cB);
                }
            }
            if (bt + 2 < NBATCH) {   // prefetch batch bt+2
                const float2* xb = xc + (size_t)(bt + 2) * PF * F2STRIDE;
                #pragma unroll
                for (int k = 0; k < PF; ++k) bufA[k] = xb[k * F2STRIDE];
            }
            // compute batch bt+1 from bufB
            #pragma unroll
            for (int k = 0; k < PF; ++k) {
                float2 xv = bufB[k];
                unsigned long long x01 = packf2(xv.x, xv.y);
                FMA2(ssq, x01, x01);
                unsigned long long xb0 = packf2(xv.x, xv.x);
                unsigned long long xb1 = packf2(xv.y, xv.y);
                const double2* crow = reinterpret_cast<const double2*>(
                    &sCl[((bt + 1) * PF + k) * ROWF]);
                #pragma unroll
                for (int j = 0; j < 7; ++j) {
                    double2 d = crow[j];
                    unsigned long long cA = __double_as_longlong(d.x);
                    unsigned long long cB = __double_as_longlong(d.y);
                    FMA2(acc0[2 * j],     xb0, cA);
                    FMA2(acc1[2 * j],     xb1, cA);
                    FMA2(acc0[2 * j + 1], xb0, cB);
                    FMA2(acc1[2 * j + 1], xb1, cB);
                }
            }
        }
    }

    // ---------------- epilogue: normalize, softmax, store, loss ----------------
    float q0, q1;
    unpackf2(ssq, q0, q1);
    float inv0 = 1.f / fmaxf(sqrtf(q0), 1e-12f);
    float inv1 = 1.f / fmaxf(sqrtf(q1), 1e-12f);

    float s0[N_ + 1], s1[N_ + 1];
    #pragma unroll
    for (int j = 0; j < NPAIR; ++j) {
        float a, bb;
        unpackf2(acc0[j], a, bb);
        s0[2 * j] = a * inv0;  s0[2 * j + 1] = bb * inv0;
        unpackf2(acc1[j], a, bb);
        s1[2 * j] = a * inv1;  s1[2 * j + 1] = bb * inv1;
    }
    float m0 = -1e30f, m1 = -1e30f;
    #pragma unroll
    for (int n = 0; n < N_; ++n) {
        m0 = fmaxf(m0, s0[n]);
        m1 = fmaxf(m1, s1[n]);
    }
    float t0 = 0.f, t1 = 0.f;
    #pragma unroll
    for (int n = 0; n < N_; ++n) {
        t0 += __expf(2.f * (s0[n] - m0));
        t1 += __expf(2.f * (s1[n] - m1));
    }
    float r0 = 1.f / t0, r1 = 1.f / t1;

    float* po = out + probs_off + (size_t)b * N_ * HW_ + hw;
    float lp = 0.f;
    #pragma unroll
    for (int n = 0; n < N_; ++n) {
        float pv0 = __expf(2.f * (s0[n] - m0)) * r0;
        float pv1 = __expf(2.f * (s1[n] - m1)) * r1;
        po[(size_t)n * HW_]     = pv0;
        po[(size_t)n * HW_ + 1] = pv1;
        lp += pv0 * s0[n] + pv1 * s1[n];
    }

    // loss partial: warp reduce + one atomic per warp
    #pragma unroll
    for (int o = 16; o; o >>= 1) lp += __shfl_xor_sync(0xffffffffu, lp, o);
    if ((threadIdx.x & 31) == 0) atomicAdd(&g_loss, (double)lp);

    // last-block finalization
    __shared__ unsigned s_last;
    __syncthreads();
    if (threadIdx.x == 0) {
        __threadfence();
        s_last = (atomicAdd(&g_done, 1u) == (unsigned)(nblocks - 1));
    }
    __syncthreads();
    if (s_last && threadIdx.x == 0) {
        double L = *(volatile double*)&g_loss;
        if (write_loss) out[0] = (float)(-L / (double)NPIX);
        g_done = 0u;
    }
}

// ---------------------------------------------------------------------------
extern "C" void kernel_launch(void* const* d_in, const int* in_sizes, int n_in,
                              void* d_out, int out_size) {
    const float* x        = (const float*)d_in[0];
    const float* clusters = (const float*)d_in[1];
    if (in_sizes[0] == N_ * C_) {
        x        = (const float*)d_in[1];
        clusters = (const float*)d_in[0];
    }
    float* out = (float*)d_out;

    int probs_off  = out_size - (B_ * N_ * HW_);
    if (probs_off < 0) probs_off = 0;
    int write_loss = (probs_off >= 1) ? 1 : 0;

    int nblocks = (NPIX / 2) / 128;          // 392
    prep_kernel<<<N_, 512>>>(clusters);
    main_kernel<<<nblocks, 128>>>(x, out, probs_off, write_loss, nblocks);
}